// round 5
// baseline (speedup 1.0000x reference)
#include <cuda_runtime.h>

// QuantumKernelLayer collapsed to 6 cosines/sample:
//   a = x0+p0, b = x1+p1
//   z0 = 0.5*[(1-sin b)*cos(p2-a) + (1+sin b)*cos(p2+a)]
//   z1 = 0.5*[cos(a)*(cos(p3-b)+cos(p3+b)) - (cos(p3-b)-cos(p3+b))]
// HBM-streaming bound. Persistent grid-stride kernel (no wave
// transitions) with a 2-stage software pipeline: next group's 3
// LDG.128 are issued before current group's compute+store, keeping
// DRAM requests continuously in flight. ILP=2 samples/group.

__device__ __forceinline__ float2 qkl_one(float x0, float x1,
                                          float p0, float p1,
                                          float p2, float p3)
{
    float a = x0 + p0;
    float b = x1 + p1;

    float cu = __cosf(p2 - a);
    float cv = __cosf(p2 + a);
    float sb = __sinf(b);
    float ca = __cosf(a);
    float cw = __cosf(p3 - b);
    float ct = __cosf(p3 + b);

    float z0 = 0.5f * ((1.0f - sb) * cu + (1.0f + sb) * cv);
    float z1 = 0.5f * (ca * (cw + ct) - (cw - ct));
    return make_float2(z0, z1);
}

__global__ __launch_bounds__(256)
void qkl_persist(const float4* __restrict__ x2,  // 2 samples per float4
                 const float4* __restrict__ p1v, // 1 sample per float4
                 float4* __restrict__ o2,        // 2 samples per float4
                 int ngroups)                    // n/2 complete groups
{
    int i = blockIdx.x * blockDim.x + threadIdx.x;
    int stride = gridDim.x * blockDim.x;

    if (i >= ngroups) return;

    // Prologue: load group i
    float4 xa = x2[i];
    float4 pa = p1v[2 * i];
    float4 pb = p1v[2 * i + 1];

    for (;;) {
        int j = i + stride;
        bool more = (j < ngroups);
        int jj = more ? j : i;   // clamped prefetch index (always valid)

        // Prefetch next group's loads BEFORE current compute/store
        float4 nxa = x2[jj];
        float4 npa = p1v[2 * jj];
        float4 npb = p1v[2 * jj + 1];

        float2 r0 = qkl_one(xa.x, xa.y, pa.x, pa.y, pa.z, pa.w);
        float2 r1 = qkl_one(xa.z, xa.w, pb.x, pb.y, pb.z, pb.w);
        o2[i] = make_float4(r0.x, r0.y, r1.x, r1.y);

        if (!more) break;
        xa = nxa; pa = npa; pb = npb;
        i = j;
    }
}

// Tail kernel for odd n (not taken for B=4194304; kept for generality)
__global__ void qkl_tail(const float* __restrict__ xf,
                         const float* __restrict__ pf,
                         float* __restrict__ of,
                         int start, int n)
{
    int k = start + blockIdx.x * blockDim.x + threadIdx.x;
    if (k >= n) return;
    float2 r = qkl_one(xf[2 * k], xf[2 * k + 1],
                       pf[4 * k], pf[4 * k + 1],
                       pf[4 * k + 2], pf[4 * k + 3]);
    of[2 * k] = r.x;
    of[2 * k + 1] = r.y;
}

extern "C" void kernel_launch(void* const* d_in, const int* in_sizes, int n_in,
                              void* d_out, int out_size)
{
    const float4* x = (const float4*)d_in[0];   // x: [B,2] float32
    const float4* p = (const float4*)d_in[1];   // parameters: [B,4] float32
    float4* out = (float4*)d_out;               // out: [B,2] float32

    int n = in_sizes[0] / 2;                    // B samples
    int ngroups = n / 2;                        // complete 2-sample groups

    // Persistent grid: 8 CTAs/SM x 148 SMs (GB300 has 152; 148 keeps the
    // model's wave math conservative and any extra SMs just idle less work)
    int threads = 256;
    int blocks = 1184;                           // 8 * 148
    int total_threads = blocks * threads;
    if (ngroups < total_threads)                 // small-n fallback
        blocks = (ngroups + threads - 1) / threads;

    qkl_persist<<<blocks, threads>>>(x, p, out, ngroups);

    if (n & 1) {
        qkl_tail<<<1, 32>>>((const float*)x, (const float*)p, (float*)out,
                            n - 1, n);
    }
}

// round 6
// speedup vs baseline: 1.0025x; 1.0025x over previous
#include <cuda_runtime.h>

// QuantumKernelLayer collapsed to 6 cosines/sample:
//   a = x0+p0, b = x1+p1
//   z0 = 0.5*[(1-sin b)*cos(p2-a) + (1+sin b)*cos(p2+a)]
//   z1 = 0.5*[cos(a)*(cos(p3-b)+cos(p3+b)) - (cos(p3-b)-cos(p3+b))]
// HBM-streaming bound. Winning recipe (R4): ILP=2 samples/thread,
// 3 front-batched LDG.128, low register count, maximum resident warps.
// R5 showed per-thread pipelining hurts (regs up, occ down) — reverted.
// This round: 128-thread blocks for finer CTA scheduling granularity
// (smoother wave drain across the two L2 dies), same 30-reg body.

__device__ __forceinline__ float2 qkl_one(float x0, float x1,
                                          float p0, float p1,
                                          float p2, float p3)
{
    float a = x0 + p0;
    float b = x1 + p1;

    float cu = __cosf(p2 - a);
    float cv = __cosf(p2 + a);
    float sb = __sinf(b);
    float ca = __cosf(a);
    float cw = __cosf(p3 - b);
    float ct = __cosf(p3 + b);

    float z0 = 0.5f * ((1.0f - sb) * cu + (1.0f + sb) * cv);
    float z1 = 0.5f * (ca * (cw + ct) - (cw - ct));
    return make_float2(z0, z1);
}

__global__ __launch_bounds__(128)
void qkl_kernel2(const float4* __restrict__ x2,  // 2 samples per float4
                 const float4* __restrict__ p1v, // 1 sample per float4
                 float4* __restrict__ o2,        // 2 samples per float4
                 int n)                          // total samples
{
    int i = blockIdx.x * blockDim.x + threadIdx.x;  // group of 2 samples
    int s = i * 2;

    if (s + 2 <= n) {
        // Front-batched loads: 3 independent LDG.128
        float4 xa = x2[i];
        float4 pa = p1v[2 * i];
        float4 pb = p1v[2 * i + 1];

        float2 r0 = qkl_one(xa.x, xa.y, pa.x, pa.y, pa.z, pa.w);
        float2 r1 = qkl_one(xa.z, xa.w, pb.x, pb.y, pb.z, pb.w);

        o2[i] = make_float4(r0.x, r0.y, r1.x, r1.y);
    } else if (s < n) {
        // Scalar tail (never taken for B=4194304, kept for safety)
        const float* xf = (const float*)x2;
        const float* pf = (const float*)p1v;
        float* of = (float*)o2;
        for (int k = s; k < n; k++) {
            float2 r = qkl_one(xf[2 * k], xf[2 * k + 1],
                               pf[4 * k], pf[4 * k + 1],
                               pf[4 * k + 2], pf[4 * k + 3]);
            of[2 * k] = r.x;
            of[2 * k + 1] = r.y;
        }
    }
}

extern "C" void kernel_launch(void* const* d_in, const int* in_sizes, int n_in,
                              void* d_out, int out_size)
{
    const float4* x = (const float4*)d_in[0];   // x: [B,2] float32
    const float4* p = (const float4*)d_in[1];   // parameters: [B,4] float32
    float4* out = (float4*)d_out;               // out: [B,2] float32

    int n = in_sizes[0] / 2;                    // B samples
    int threads = 128;
    int groups = (n + 1) / 2;
    int blocks = (groups + threads - 1) / threads;
    qkl_kernel2<<<blocks, threads>>>(x, p, out, n);
}

// round 7
// speedup vs baseline: 1.0233x; 1.0207x over previous
#include <cuda_runtime.h>

// QuantumKernelLayer collapsed to 6 cosines/sample:
//   a = x0+p0, b = x1+p1
//   z0 = 0.5*[(1-sin b)*cos(p2-a) + (1+sin b)*cos(p2+a)]
//   z1 = 0.5*[cos(a)*(cos(p3-b)+cos(p3+b)) - (cos(p3-b)-cos(p3+b))]
// HBM-streaming bound. Converged config (R4 sweep winner):
//   ILP=2 samples/thread, 3 front-batched LDG.128 + 1 STG.128,
//   256-thread blocks, 30 regs, max resident warps.
// Measured: 19.46us kernel, DRAM 73.4%, ~95% of the ~18.5us
// mixed-stream floor (100.7MB read @ ~7.2TB/s effective).
// Rejected by measurement: ILP=4 (R2), streaming hints (R3),
// persistent+prefetch pipeline (R5), 128-thread blocks (R6).

__device__ __forceinline__ float2 qkl_one(float x0, float x1,
                                          float p0, float p1,
                                          float p2, float p3)
{
    float a = x0 + p0;
    float b = x1 + p1;

    float cu = __cosf(p2 - a);
    float cv = __cosf(p2 + a);
    float sb = __sinf(b);
    float ca = __cosf(a);
    float cw = __cosf(p3 - b);
    float ct = __cosf(p3 + b);

    float z0 = 0.5f * ((1.0f - sb) * cu + (1.0f + sb) * cv);
    float z1 = 0.5f * (ca * (cw + ct) - (cw - ct));
    return make_float2(z0, z1);
}

__global__ __launch_bounds__(256)
void qkl_kernel2(const float4* __restrict__ x2,  // 2 samples per float4
                 const float4* __restrict__ p1v, // 1 sample per float4
                 float4* __restrict__ o2,        // 2 samples per float4
                 int n)                          // total samples
{
    int i = blockIdx.x * blockDim.x + threadIdx.x;  // group of 2 samples
    int s = i * 2;

    if (s + 2 <= n) {
        // Front-batched loads: 3 independent LDG.128
        float4 xa = x2[i];
        float4 pa = p1v[2 * i];
        float4 pb = p1v[2 * i + 1];

        float2 r0 = qkl_one(xa.x, xa.y, pa.x, pa.y, pa.z, pa.w);
        float2 r1 = qkl_one(xa.z, xa.w, pb.x, pb.y, pb.z, pb.w);

        o2[i] = make_float4(r0.x, r0.y, r1.x, r1.y);
    } else if (s < n) {
        // Scalar tail (never taken for B=4194304, kept for safety)
        const float* xf = (const float*)x2;
        const float* pf = (const float*)p1v;
        float* of = (float*)o2;
        for (int k = s; k < n; k++) {
            float2 r = qkl_one(xf[2 * k], xf[2 * k + 1],
                               pf[4 * k], pf[4 * k + 1],
                               pf[4 * k + 2], pf[4 * k + 3]);
            of[2 * k] = r.x;
            of[2 * k + 1] = r.y;
        }
    }
}

extern "C" void kernel_launch(void* const* d_in, const int* in_sizes, int n_in,
                              void* d_out, int out_size)
{
    const float4* x = (const float4*)d_in[0];   // x: [B,2] float32
    const float4* p = (const float4*)d_in[1];   // parameters: [B,4] float32
    float4* out = (float4*)d_out;               // out: [B,2] float32

    int n = in_sizes[0] / 2;                    // B samples
    int threads = 256;
    int groups = (n + 1) / 2;
    int blocks = (groups + threads - 1) / threads;
    qkl_kernel2<<<blocks, threads>>>(x, p, out, n);
}

// round 8
// speedup vs baseline: 1.0326x; 1.0091x over previous
#include <cuda_runtime.h>

// QuantumKernelLayer collapsed to 6 cosines/sample:
//   a = x0+p0, b = x1+p1
//   z0 = 0.5*[(1-sin b)*cos(p2-a) + (1+sin b)*cos(p2+a)]
//   z1 = 0.5*[cos(a)*(cos(p3-b)+cos(p3+b)) - (cos(p3-b)-cos(p3+b))]
// HBM-streaming bound, ~95% of the 18.5us read floor already.
// Winning recipe: ILP=2 samples/thread, 3 front-batched LDG.128 +
// 1 STG.128, 30 regs. This round tests the last (ILP x blocksize)
// cell: 512-thread blocks (4 CTAs/SM, larger per-CTA LDG batches).

__device__ __forceinline__ float2 qkl_one(float x0, float x1,
                                          float p0, float p1,
                                          float p2, float p3)
{
    float a = x0 + p0;
    float b = x1 + p1;

    float cu = __cosf(p2 - a);
    float cv = __cosf(p2 + a);
    float sb = __sinf(b);
    float ca = __cosf(a);
    float cw = __cosf(p3 - b);
    float ct = __cosf(p3 + b);

    float z0 = 0.5f * ((1.0f - sb) * cu + (1.0f + sb) * cv);
    float z1 = 0.5f * (ca * (cw + ct) - (cw - ct));
    return make_float2(z0, z1);
}

__global__ __launch_bounds__(512)
void qkl_kernel2w(const float4* __restrict__ x2,  // 2 samples per float4
                  const float4* __restrict__ p1v, // 1 sample per float4
                  float4* __restrict__ o2,        // 2 samples per float4
                  int n)                          // total samples
{
    int i = blockIdx.x * blockDim.x + threadIdx.x;  // group of 2 samples
    int s = i * 2;

    if (s + 2 <= n) {
        // Front-batched loads: 3 independent LDG.128
        float4 xa = x2[i];
        float4 pa = p1v[2 * i];
        float4 pb = p1v[2 * i + 1];

        float2 r0 = qkl_one(xa.x, xa.y, pa.x, pa.y, pa.z, pa.w);
        float2 r1 = qkl_one(xa.z, xa.w, pb.x, pb.y, pb.z, pb.w);

        o2[i] = make_float4(r0.x, r0.y, r1.x, r1.y);
    } else if (s < n) {
        // Scalar tail (never taken for B=4194304, kept for safety)
        const float* xf = (const float*)x2;
        const float* pf = (const float*)p1v;
        float* of = (float*)o2;
        for (int k = s; k < n; k++) {
            float2 r = qkl_one(xf[2 * k], xf[2 * k + 1],
                               pf[4 * k], pf[4 * k + 1],
                               pf[4 * k + 2], pf[4 * k + 3]);
            of[2 * k] = r.x;
            of[2 * k + 1] = r.y;
        }
    }
}

extern "C" void kernel_launch(void* const* d_in, const int* in_sizes, int n_in,
                              void* d_out, int out_size)
{
    const float4* x = (const float4*)d_in[0];   // x: [B,2] float32
    const float4* p = (const float4*)d_in[1];   // parameters: [B,4] float32
    float4* out = (float4*)d_out;               // out: [B,2] float32

    int n = in_sizes[0] / 2;                    // B samples
    int threads = 512;
    int groups = (n + 1) / 2;
    int blocks = (groups + threads - 1) / threads;
    qkl_kernel2w<<<blocks, threads>>>(x, p, out, n);
}